// round 10
// baseline (speedup 1.0000x reference)
#include <cuda_runtime.h>
#include <cuda_fp16.h>

// Factorized ray-marching: x@W1+b1 = p1 + alpha*u.
// R10: 16-lane groups (2 rows/warp) to halve phase-B operand registers and
// double warp count. Block = 16 rows / 8 warps. Phase A: warp = 16 rows x
// 32 cols, A-frags loaded inside kt loop, norm deferred to f32 post-scale.
// Target <=40 regs -> 6 blocks/SM.

#define D_DIM 128
#define H_DIM 256
#define KT    8
#define NT    32
#define UPAD  264            // halves per u row; bank-conflict-free (stride 4 banks)

__device__ __half2 g_p1h2[H_DIM / 2];
__device__ __half2 g_w2h2[H_DIM / 2];
__device__ uint2   g_Bfrag[KT * NT * 32];   // 64 KB: W1 in HMMA B-fragment layout

static __device__ __forceinline__ float tanh_fast(float x) {
    float y; asm("tanh.approx.f32 %0, %1;" : "=f"(y) : "f"(x)); return y;
}
static __device__ __forceinline__ __half2 tanh2_fast(__half2 x) {
    __half2 y;
    asm("tanh.approx.f16x2 %0, %1;" : "=r"(*(unsigned*)&y) : "r"(*(unsigned*)&x));
    return y;
}
static __device__ __forceinline__ unsigned h2bits(__half2 v) { return *(unsigned*)&v; }
static __device__ __forceinline__ void mma16816(float& c0, float& c1, float& c2, float& c3,
                                                unsigned a0, unsigned a1, unsigned a2, unsigned a3,
                                                unsigned b0, unsigned b1) {
    asm volatile("mma.sync.aligned.m16n8k16.row.col.f32.f16.f16.f32 "
                 "{%0,%1,%2,%3}, {%4,%5,%6,%7}, {%8,%9}, {%0,%1,%2,%3};"
                 : "+f"(c0), "+f"(c1), "+f"(c2), "+f"(c3)
                 : "r"(a0), "r"(a1), "r"(a2), "r"(a3), "r"(b0), "r"(b1));
}

// prep (grid 9, block 1024): block 0 -> p1 (4-way d-split reduction) + half
// copies; blocks 1..8 -> W1 B-fragment packing.
__global__ __launch_bounds__(1024)
void prep_kernel(const float* __restrict__ pivot,
                 const float* __restrict__ W1,
                 const float* __restrict__ b1,
                 const float* __restrict__ w2) {
    if (blockIdx.x == 0) {
        __shared__ float red[4][H_DIM];
        __shared__ float sp1[H_DIM];
        const int j  = threadIdx.x & 255;
        const int dg = threadIdx.x >> 8;
        float s = 0.f;
        const int d0 = dg * 32;
#pragma unroll 8
        for (int d = d0; d < d0 + 32; ++d)
            s = fmaf(pivot[d], W1[(size_t)d * H_DIM + j], s);
        red[dg][j] = s;
        __syncthreads();
        if (dg == 0)
            sp1[j] = red[0][j] + red[1][j] + red[2][j] + red[3][j] + b1[j];
        __syncthreads();
        if (threadIdx.x < H_DIM / 2) {
            g_p1h2[threadIdx.x] = __floats2half2_rn(sp1[2 * threadIdx.x],
                                                    sp1[2 * threadIdx.x + 1]);
            g_w2h2[threadIdx.x] = __floats2half2_rn(w2[2 * threadIdx.x],
                                                    w2[2 * threadIdx.x + 1]);
        }
    } else {
        const int e = (blockIdx.x - 1) * 1024 + threadIdx.x;   // 0..8191
        const int tile = e >> 5;
        const int lane = e & 31;
        const int kt = tile / NT;
        const int nt = tile % NT;
        const int g = lane >> 2, t4 = lane & 3;
        const int k0 = kt * 16 + t4 * 2;
        const int col = nt * 8 + g;
        __half2 b0v = __floats2half2_rn(W1[(size_t)k0 * H_DIM + col],
                                        W1[(size_t)(k0 + 1) * H_DIM + col]);
        __half2 b1v = __floats2half2_rn(W1[(size_t)(k0 + 8) * H_DIM + col],
                                        W1[(size_t)(k0 + 9) * H_DIM + col]);
        g_Bfrag[tile * 32 + lane] = make_uint2(h2bits(b0v), h2bits(b1v));
    }
}

// ============== fused main kernel: block = 16 rows, 8 warps ==============
__global__ __launch_bounds__(256, 6)
void main_kernel(const float* __restrict__ r,
                 const float* __restrict__ s_in,
                 const float* __restrict__ pivot,
                 const float* __restrict__ b2,
                 const int* __restrict__ n_iter_ptr,
                 float* __restrict__ out,
                 int B) {
    __shared__ __half u_sh[16][UPAD];     // 16 x 264 halves = 8.25 KB

    const int lane = threadIdx.x & 31;
    const int wib  = threadIdx.x >> 5;
    const int base_row = blockIdx.x * 16;

    // ---------- Phase A: GEMM. warp = 16 rows x 32 cols (4 n-tiles) ----------
    {
        const int ntg = wib * 4;                   // this warp's first n-tile
        const int g4 = lane >> 2, t4 = lane & 3;
        const float* pA = r + (size_t)(base_row + g4) * D_DIM;
        const float* pB = pA + (size_t)8 * D_DIM;

        float acc[4][4];
#pragma unroll
        for (int t = 0; t < 4; ++t)
#pragma unroll
            for (int q = 0; q < 4; ++q) acc[t][q] = 0.f;

        float ssl = 0.f, ssh = 0.f;
#pragma unroll
        for (int kt = 0; kt < KT; ++kt) {
            const int base = kt * 16 + t4 * 2;
            float2 v0 = *(const float2*)(pA + base);
            float2 v1 = *(const float2*)(pB + base);
            float2 v2 = *(const float2*)(pA + base + 8);
            float2 v3 = *(const float2*)(pB + base + 8);
            ssl = fmaf(v0.x, v0.x, fmaf(v0.y, v0.y, fmaf(v2.x, v2.x, fmaf(v2.y, v2.y, ssl))));
            ssh = fmaf(v1.x, v1.x, fmaf(v1.y, v1.y, fmaf(v3.x, v3.x, fmaf(v3.y, v3.y, ssh))));
            const unsigned a0 = h2bits(__floats2half2_rn(v0.x, v0.y));
            const unsigned a1 = h2bits(__floats2half2_rn(v1.x, v1.y));
            const unsigned a2 = h2bits(__floats2half2_rn(v2.x, v2.y));
            const unsigned a3 = h2bits(__floats2half2_rn(v3.x, v3.y));

            const uint2* bb = g_Bfrag + (size_t)(kt * NT + ntg) * 32 + lane;
            uint2 bf[4];
#pragma unroll
            for (int t = 0; t < 4; ++t) bf[t] = __ldg(bb + t * 32);
#pragma unroll
            for (int t = 0; t < 4; ++t)
                mma16816(acc[t][0], acc[t][1], acc[t][2], acc[t][3],
                         a0, a1, a2, a3, bf[t].x, bf[t].y);
        }

        // quad-reduce square sums, scale accumulators in f32, store as half
        ssl += __shfl_xor_sync(0xffffffffu, ssl, 1);
        ssl += __shfl_xor_sync(0xffffffffu, ssl, 2);
        ssh += __shfl_xor_sync(0xffffffffu, ssh, 1);
        ssh += __shfl_xor_sync(0xffffffffu, ssh, 2);
        const float invl = rsqrtf(ssl);
        const float invh = rsqrtf(ssh);
#pragma unroll
        for (int t = 0; t < 4; ++t) {
            const int col = (ntg + t) * 8 + t4 * 2;
            *(__half2*)&u_sh[g4][col]     = __floats2half2_rn(acc[t][0] * invl, acc[t][1] * invl);
            *(__half2*)&u_sh[g4 + 8][col] = __floats2half2_rn(acc[t][2] * invh, acc[t][3] * invh);
        }
    }
    __syncthreads();

    // ---------- Phase B: 20-step recurrence, 2 rows/warp (16-lane groups) ----------
    const int l16 = lane & 15;
    const int lrow = wib * 2 + (lane >> 4);
    const int row = base_row + lrow;
    if (row >= B) return;

    __half2 u2[8], p12[8], w22[8];
    {
        const uint4* up = (const uint4*)(&u_sh[lrow][0]) + l16 * 2;
        const uint4* pp = (const uint4*)g_p1h2 + l16 * 2;
        const uint4* wp = (const uint4*)g_w2h2 + l16 * 2;
#pragma unroll
        for (int v = 0; v < 2; ++v) {
            uint4 uu = up[v];
            uint4 aa = __ldg(pp + v);
            uint4 bb = __ldg(wp + v);
            u2[v * 4 + 0] = *(__half2*)&uu.x; u2[v * 4 + 1] = *(__half2*)&uu.y;
            u2[v * 4 + 2] = *(__half2*)&uu.z; u2[v * 4 + 3] = *(__half2*)&uu.w;
            p12[v * 4 + 0] = *(__half2*)&aa.x; p12[v * 4 + 1] = *(__half2*)&aa.y;
            p12[v * 4 + 2] = *(__half2*)&aa.z; p12[v * 4 + 3] = *(__half2*)&aa.w;
            w22[v * 4 + 0] = *(__half2*)&bb.x; w22[v * 4 + 1] = *(__half2*)&bb.y;
            w22[v * 4 + 2] = *(__half2*)&bb.z; w22[v * 4 + 3] = *(__half2*)&bb.w;
        }
    }

    const float b2v = b2[0];
    const int n = n_iter_ptr ? *n_iter_ptr : 20;
    const __half2 h2z = __floats2half2_rn(0.f, 0.f);

    float alpha = 0.f;
    for (int it = 0; it < n; ++it) {
        const __half2 a2h = __float2half2_rn(alpha);
        __half2 acc2a = h2z, acc2b = h2z;
#pragma unroll
        for (int q = 0; q < 8; q += 2) {
            __half2 za = __hfma2(a2h, u2[q],     p12[q]);
            __half2 zb = __hfma2(a2h, u2[q + 1], p12[q + 1]);
            acc2a = __hfma2(tanh2_fast(za), w22[q],     acc2a);
            acc2b = __hfma2(tanh2_fast(zb), w22[q + 1], acc2b);
        }
        __half2 acc2 = __hadd2(acc2a, acc2b);
        float accf = __low2float(acc2) + __high2float(acc2);
        accf += __shfl_xor_sync(0xffffffffu, accf, 1);
        accf += __shfl_xor_sync(0xffffffffu, accf, 2);
        accf += __shfl_xor_sync(0xffffffffu, accf, 4);
        accf += __shfl_xor_sync(0xffffffffu, accf, 8);
        alpha += 0.05f * (1.0f + tanh_fast(accf + b2v));
    }

    // tail: r reload (lane owns dims 8*l16 .. 8*l16+7), norm, sigmoid, output
    const float4* rv4 = (const float4*)(r + (size_t)row * D_DIM) + l16 * 2;
    float4 rv0 = rv4[0];
    float4 rv1 = rv4[1];
    float ss = fmaf(rv0.x, rv0.x, fmaf(rv0.y, rv0.y, fmaf(rv0.z, rv0.z, rv0.w * rv0.w)));
    ss = fmaf(rv1.x, rv1.x, fmaf(rv1.y, rv1.y, fmaf(rv1.z, rv1.z, fmaf(rv1.w, rv1.w, ss))));
    ss += __shfl_xor_sync(0xffffffffu, ss, 1);
    ss += __shfl_xor_sync(0xffffffffu, ss, 2);
    ss += __shfl_xor_sync(0xffffffffu, ss, 4);
    ss += __shfl_xor_sync(0xffffffffu, ss, 8);
    const float inv_norm = rsqrtf(ss);

    const float sv = s_in[row];
    const float sig = 1.0f / (1.0f + __expf(-sv));
    const float fscale = sig * alpha * inv_norm;

    const float4* pv4 = (const float4*)pivot + l16 * 2;
    float4* ov4 = (float4*)(out + (size_t)row * D_DIM) + l16 * 2;
    float4 pv = pv4[0];
    float4 o;
    o.x = fmaf(fscale, rv0.x, pv.x);
    o.y = fmaf(fscale, rv0.y, pv.y);
    o.z = fmaf(fscale, rv0.z, pv.z);
    o.w = fmaf(fscale, rv0.w, pv.w);
    ov4[0] = o;
    pv = pv4[1];
    o.x = fmaf(fscale, rv1.x, pv.x);
    o.y = fmaf(fscale, rv1.y, pv.y);
    o.z = fmaf(fscale, rv1.z, pv.z);
    o.w = fmaf(fscale, rv1.w, pv.w);
    ov4[1] = o;
}

extern "C" void kernel_launch(void* const* d_in, const int* in_sizes, int n_in,
                              void* d_out, int out_size) {
    const float* r     = (const float*)d_in[0];   // [B,128]
    const float* s     = (const float*)d_in[1];   // [B,1]
    const float* pivot = (const float*)d_in[2];   // [128]
    const float* W1    = (const float*)d_in[3];   // [128,256]
    const float* b1    = (const float*)d_in[4];   // [256]
    const float* w2    = (const float*)d_in[5];   // [256]
    const float* b2    = (const float*)d_in[6];   // [1]
    const int* n_iter  = (n_in > 7) ? (const int*)d_in[7] : nullptr;
    float* out = (float*)d_out;

    const int B = in_sizes[0] / D_DIM;

    prep_kernel<<<9, 1024>>>(pivot, W1, b1, w2);

    const int blocks = (B + 15) / 16;
    main_kernel<<<blocks, 256>>>(r, s, pivot, b2, n_iter, out, B);
}

// round 11
// speedup vs baseline: 1.1185x; 1.1185x over previous
#include <cuda_runtime.h>
#include <cuda_fp16.h>

// Factorized ray-marching: x@W1+b1 = p1 + alpha*u.
// R11: r staged to smem ONCE per block (normalized, half) -> Phase A reads
// A-fragments via conflict-free LDS.32 instead of 8-way-uncoalesced LDGs.
// Block = 16 rows / 8 warps; Phase A warp = 16 rows x 32 cols (HMMA);
// Phase B: 2 rows/warp, 16-lane groups, f16x2 tanh.

#define D_DIM 128
#define H_DIM 256
#define KT    8
#define NT    32
#define UPAD  264            // halves per u row
#define RPAD  136            // halves per staged r row (4-bank row offset)

__device__ __half2 g_p1h2[H_DIM / 2];
__device__ __half2 g_w2h2[H_DIM / 2];
__device__ uint2   g_Bfrag[KT * NT * 32];   // 64 KB: W1 in HMMA B-fragment layout

static __device__ __forceinline__ float tanh_fast(float x) {
    float y; asm("tanh.approx.f32 %0, %1;" : "=f"(y) : "f"(x)); return y;
}
static __device__ __forceinline__ __half2 tanh2_fast(__half2 x) {
    __half2 y;
    asm("tanh.approx.f16x2 %0, %1;" : "=r"(*(unsigned*)&y) : "r"(*(unsigned*)&x));
    return y;
}
static __device__ __forceinline__ unsigned h2bits(__half2 v) { return *(unsigned*)&v; }
static __device__ __forceinline__ void mma16816(float& c0, float& c1, float& c2, float& c3,
                                                unsigned a0, unsigned a1, unsigned a2, unsigned a3,
                                                unsigned b0, unsigned b1) {
    asm volatile("mma.sync.aligned.m16n8k16.row.col.f32.f16.f16.f32 "
                 "{%0,%1,%2,%3}, {%4,%5,%6,%7}, {%8,%9}, {%0,%1,%2,%3};"
                 : "+f"(c0), "+f"(c1), "+f"(c2), "+f"(c3)
                 : "r"(a0), "r"(a1), "r"(a2), "r"(a3), "r"(b0), "r"(b1));
}

// prep (grid 9, block 1024): block 0 -> p1 (4-way d-split reduction) + half
// copies; blocks 1..8 -> W1 B-fragment packing.
__global__ __launch_bounds__(1024)
void prep_kernel(const float* __restrict__ pivot,
                 const float* __restrict__ W1,
                 const float* __restrict__ b1,
                 const float* __restrict__ w2) {
    if (blockIdx.x == 0) {
        __shared__ float red[4][H_DIM];
        __shared__ float sp1[H_DIM];
        const int j  = threadIdx.x & 255;
        const int dg = threadIdx.x >> 8;
        float s = 0.f;
        const int d0 = dg * 32;
#pragma unroll 8
        for (int d = d0; d < d0 + 32; ++d)
            s = fmaf(pivot[d], W1[(size_t)d * H_DIM + j], s);
        red[dg][j] = s;
        __syncthreads();
        if (dg == 0)
            sp1[j] = red[0][j] + red[1][j] + red[2][j] + red[3][j] + b1[j];
        __syncthreads();
        if (threadIdx.x < H_DIM / 2) {
            g_p1h2[threadIdx.x] = __floats2half2_rn(sp1[2 * threadIdx.x],
                                                    sp1[2 * threadIdx.x + 1]);
            g_w2h2[threadIdx.x] = __floats2half2_rn(w2[2 * threadIdx.x],
                                                    w2[2 * threadIdx.x + 1]);
        }
    } else {
        const int e = (blockIdx.x - 1) * 1024 + threadIdx.x;   // 0..8191
        const int tile = e >> 5;
        const int lane = e & 31;
        const int kt = tile / NT;
        const int nt = tile % NT;
        const int g = lane >> 2, t4 = lane & 3;
        const int k0 = kt * 16 + t4 * 2;
        const int col = nt * 8 + g;
        __half2 b0v = __floats2half2_rn(W1[(size_t)k0 * H_DIM + col],
                                        W1[(size_t)(k0 + 1) * H_DIM + col]);
        __half2 b1v = __floats2half2_rn(W1[(size_t)(k0 + 8) * H_DIM + col],
                                        W1[(size_t)(k0 + 9) * H_DIM + col]);
        g_Bfrag[tile * 32 + lane] = make_uint2(h2bits(b0v), h2bits(b1v));
    }
}

// ============== fused main kernel: block = 16 rows, 8 warps ==============
__global__ __launch_bounds__(256, 6)
void main_kernel(const float* __restrict__ r,
                 const float* __restrict__ s_in,
                 const float* __restrict__ pivot,
                 const float* __restrict__ b2,
                 const int* __restrict__ n_iter_ptr,
                 float* __restrict__ out,
                 int B) {
    __shared__ __half u_sh[16][UPAD];     // 8.25 KB
    __shared__ __half r_sh[16][RPAD];     // 4.25 KB: normalized r rows (half)
    __shared__ float  inv_sh[16];

    const int lane = threadIdx.x & 31;
    const int wib  = threadIdx.x >> 5;
    const int base_row = blockIdx.x * 16;

    // ---------- Stage 0: load r rows coalesced, normalize, convert to half ----------
    // warp wib handles rows wib and wib+8 (one full row per warp pass)
#pragma unroll
    for (int p = 0; p < 2; ++p) {
        const int lrow = wib + p * 8;
        const int row = base_row + lrow;
        float4 v = (row < B) ? ((const float4*)(r + (size_t)row * D_DIM))[lane]
                             : make_float4(0.f, 0.f, 0.f, 0.f);
        float ss = fmaf(v.x, v.x, fmaf(v.y, v.y, fmaf(v.z, v.z, v.w * v.w)));
#pragma unroll
        for (int o = 16; o; o >>= 1) ss += __shfl_xor_sync(0xffffffffu, ss, o);
        const float inv = rsqrtf(ss);
        if (lane == 0) inv_sh[lrow] = inv;
        *(__half2*)&r_sh[lrow][lane * 4]     = __floats2half2_rn(v.x * inv, v.y * inv);
        *(__half2*)&r_sh[lrow][lane * 4 + 2] = __floats2half2_rn(v.z * inv, v.w * inv);
    }
    __syncthreads();

    // ---------- Phase A: HMMA. warp = 16 rows x 32 cols (4 n-tiles) ----------
    {
        const int ntg = wib * 4;
        const int g4 = lane >> 2, t4 = lane & 3;

        float acc[4][4];
#pragma unroll
        for (int t = 0; t < 4; ++t)
#pragma unroll
            for (int q = 0; q < 4; ++q) acc[t][q] = 0.f;

#pragma unroll
        for (int kt = 0; kt < KT; ++kt) {
            const int cbase = kt * 16 + t4 * 2;
            const unsigned a0 = *(const unsigned*)&r_sh[g4][cbase];
            const unsigned a1 = *(const unsigned*)&r_sh[g4 + 8][cbase];
            const unsigned a2 = *(const unsigned*)&r_sh[g4][cbase + 8];
            const unsigned a3 = *(const unsigned*)&r_sh[g4 + 8][cbase + 8];

            const uint2* bb = g_Bfrag + (size_t)(kt * NT + ntg) * 32 + lane;
            uint2 bf[4];
#pragma unroll
            for (int t = 0; t < 4; ++t) bf[t] = __ldg(bb + t * 32);
#pragma unroll
            for (int t = 0; t < 4; ++t)
                mma16816(acc[t][0], acc[t][1], acc[t][2], acc[t][3],
                         a0, a1, a2, a3, bf[t].x, bf[t].y);
        }

        // store u (A was pre-normalized; acc is final)
#pragma unroll
        for (int t = 0; t < 4; ++t) {
            const int col = (ntg + t) * 8 + t4 * 2;
            *(__half2*)&u_sh[g4][col]     = __floats2half2_rn(acc[t][0], acc[t][1]);
            *(__half2*)&u_sh[g4 + 8][col] = __floats2half2_rn(acc[t][2], acc[t][3]);
        }
    }
    __syncthreads();

    // ---------- Phase B: 20-step recurrence, 2 rows/warp (16-lane groups) ----------
    const int l16 = lane & 15;
    const int lrow = wib * 2 + (lane >> 4);
    const int row = base_row + lrow;
    if (row >= B) return;

    __half2 u2[8], p12[8], w22[8];
    {
        const uint4* up = (const uint4*)(&u_sh[lrow][0]) + l16 * 2;
        const uint4* pp = (const uint4*)g_p1h2 + l16 * 2;
        const uint4* wp = (const uint4*)g_w2h2 + l16 * 2;
#pragma unroll
        for (int v = 0; v < 2; ++v) {
            uint4 uu = up[v];
            uint4 aa = __ldg(pp + v);
            uint4 bb = __ldg(wp + v);
            u2[v * 4 + 0] = *(__half2*)&uu.x; u2[v * 4 + 1] = *(__half2*)&uu.y;
            u2[v * 4 + 2] = *(__half2*)&uu.z; u2[v * 4 + 3] = *(__half2*)&uu.w;
            p12[v * 4 + 0] = *(__half2*)&aa.x; p12[v * 4 + 1] = *(__half2*)&aa.y;
            p12[v * 4 + 2] = *(__half2*)&aa.z; p12[v * 4 + 3] = *(__half2*)&aa.w;
            w22[v * 4 + 0] = *(__half2*)&bb.x; w22[v * 4 + 1] = *(__half2*)&bb.y;
            w22[v * 4 + 2] = *(__half2*)&bb.z; w22[v * 4 + 3] = *(__half2*)&bb.w;
        }
    }

    const float b2v = b2[0];
    const int n = n_iter_ptr ? *n_iter_ptr : 20;
    const __half2 h2z = __floats2half2_rn(0.f, 0.f);

    float alpha = 0.f;
    for (int it = 0; it < n; ++it) {
        const __half2 a2h = __float2half2_rn(alpha);
        __half2 acc2a = h2z, acc2b = h2z;
#pragma unroll
        for (int q = 0; q < 8; q += 2) {
            __half2 za = __hfma2(a2h, u2[q],     p12[q]);
            __half2 zb = __hfma2(a2h, u2[q + 1], p12[q + 1]);
            acc2a = __hfma2(tanh2_fast(za), w22[q],     acc2a);
            acc2b = __hfma2(tanh2_fast(zb), w22[q + 1], acc2b);
        }
        __half2 acc2 = __hadd2(acc2a, acc2b);
        float accf = __low2float(acc2) + __high2float(acc2);
        accf += __shfl_xor_sync(0xffffffffu, accf, 1);
        accf += __shfl_xor_sync(0xffffffffu, accf, 2);
        accf += __shfl_xor_sync(0xffffffffu, accf, 4);
        accf += __shfl_xor_sync(0xffffffffu, accf, 8);
        alpha += 0.05f * (1.0f + tanh_fast(accf + b2v));
    }

    // tail: r reload (lane owns dims 8*l16 .. 8*l16+7), inv from smem, output
    const float inv_norm = inv_sh[lrow];
    const float sv = s_in[row];
    const float sig = 1.0f / (1.0f + __expf(-sv));
    const float fscale = sig * alpha * inv_norm;

    const float4* rv4 = (const float4*)(r + (size_t)row * D_DIM) + l16 * 2;
    const float4* pv4 = (const float4*)pivot + l16 * 2;
    float4* ov4 = (float4*)(out + (size_t)row * D_DIM) + l16 * 2;
#pragma unroll
    for (int j = 0; j < 2; ++j) {
        float4 rv = rv4[j];
        float4 pv = pv4[j];
        float4 o;
        o.x = fmaf(fscale, rv.x, pv.x);
        o.y = fmaf(fscale, rv.y, pv.y);
        o.z = fmaf(fscale, rv.z, pv.z);
        o.w = fmaf(fscale, rv.w, pv.w);
        ov4[j] = o;
    }
}

extern "C" void kernel_launch(void* const* d_in, const int* in_sizes, int n_in,
                              void* d_out, int out_size) {
    const float* r     = (const float*)d_in[0];   // [B,128]
    const float* s     = (const float*)d_in[1];   // [B,1]
    const float* pivot = (const float*)d_in[2];   // [128]
    const float* W1    = (const float*)d_in[3];   // [128,256]
    const float* b1    = (const float*)d_in[4];   // [256]
    const float* w2    = (const float*)d_in[5];   // [256]
    const float* b2    = (const float*)d_in[6];   // [1]
    const int* n_iter  = (n_in > 7) ? (const int*)d_in[7] : nullptr;
    float* out = (float*)d_out;

    const int B = in_sizes[0] / D_DIM;

    prep_kernel<<<9, 1024>>>(pivot, W1, b1, w2);

    const int blocks = (B + 15) / 16;
    main_kernel<<<blocks, 256>>>(r, s, pivot, b2, n_iter, out, B);
}